// round 17
// baseline (speedup 1.0000x reference)
#include <cuda_runtime.h>
#include <cuda_bf16.h>
#include <mma.h>
#include <math.h>
#include <stdint.h>

using namespace nvcuda;

#define B_ 256
#define Q_ 128
#define P_ 16
#define D_ 256
#define H_ 16
#define F_ 512
#define DK_ 16
#define MROWS (B_*Q_)        // 32768
#define SCALE_ 0.25f         // DK^-0.5
#define EPS_ 1e-5f
#define LSTRIDE ((size_t)MROWS*D_)   // per-layer q/k buffer stride (8388608)

// ---- scratch (device globals: allocation-free) ----
__device__ float g_z [MROWS*D_];
__device__ float g_t [MROWS*D_];
// split activations
__device__ __nv_bfloat16 g_ah[MROWS*F_];
__device__ __nv_bfloat16 g_al[MROWS*F_];
__device__ __nv_bfloat16 g_bh[MROWS*F_];
__device__ __nv_bfloat16 g_bl[MROWS*F_];
// per-layer Q/K splits (persist across layers for score recompute), V split (current layer)
__device__ __nv_bfloat16 g_qh[3*MROWS*D_];
__device__ __nv_bfloat16 g_ql[3*MROWS*D_];
__device__ __nv_bfloat16 g_kh[3*MROWS*D_];
__device__ __nv_bfloat16 g_kl[3*MROWS*D_];
__device__ __nv_bfloat16 g_vh[MROWS*D_];
__device__ __nv_bfloat16 g_vl[MROWS*D_];
#define WSTRIDE 524288
__device__ __nv_bfloat16 g_wh[3*WSTRIDE];
__device__ __nv_bfloat16 g_wl[3*WSTRIDE];
// weight offsets within layer: WQ 0, WK 65536, WV 131072, WO 196608, W1 262144, W2 393216

__device__ __forceinline__ void splt(float f, __nv_bfloat16& h, __nv_bfloat16& l) {
    h = __float2bfloat16(f);
    l = __float2bfloat16(f - __bfloat162float(h));
}

// ================= weight split (once per run) =================
__global__ void split_w6(const float* __restrict__ w0, const float* __restrict__ w1,
                         const float* __restrict__ w2, const float* __restrict__ w3,
                         const float* __restrict__ w4, const float* __restrict__ w5,
                         __nv_bfloat16* __restrict__ hi, __nv_bfloat16* __restrict__ lo) {
    const int sel = blockIdx.y;
    const float* src; int off, n;
    switch (sel) {
        case 0: src = w0; off = 0;      n = 65536;  break;
        case 1: src = w1; off = 65536;  n = 65536;  break;
        case 2: src = w2; off = 131072; n = 65536;  break;
        case 3: src = w3; off = 196608; n = 65536;  break;
        case 4: src = w4; off = 262144; n = 131072; break;
        default:src = w5; off = 393216; n = 131072; break;
    }
    int i = blockIdx.x * 256 + threadIdx.x;
    if (i * 4 >= n) return;
    float4 f4 = *(const float4*)(src + (size_t)i * 4);
    float f[4] = {f4.x, f4.y, f4.z, f4.w};
    __nv_bfloat16 h[4], l[4];
#pragma unroll
    for (int p = 0; p < 4; ++p) splt(f[p], h[p], l[p]);
    *(uint2*)(hi + off + (size_t)i * 4) = *(uint2*)h;
    *(uint2*)(lo + off + (size_t)i * 4) = *(uint2*)l;
}

// ================= split-bf16 WMMA GEMM, cp.async double-buffered =================
#define LDA 40
#define LDB 136
#define LDC 132
#define SA_H 0
#define SA_L 10240
#define SB_H 20480
#define SB_L 29184
#define STAGE 37888
#define SM_GEMM_BYTES (2*STAGE)

__device__ __forceinline__ void cp16(uint32_t saddr, const void* gaddr) {
    asm volatile("cp.async.cg.shared.global [%0], [%1], 16;" :: "r"(saddr), "l"(gaddr));
}

// OSPLIT=0: write fp32 C ; OSPLIT=1: write bf16 hi/lo pair (Oh/Ol)
template<int ACT, int OSPLIT>
__global__ __launch_bounds__(256)
void gemm_bf(const __nv_bfloat16* __restrict__ Ahp, const __nv_bfloat16* __restrict__ Alp,
             const __nv_bfloat16* __restrict__ Whp, const __nv_bfloat16* __restrict__ Wlp,
             const float* __restrict__ bias, float* __restrict__ C,
             __nv_bfloat16* __restrict__ Oh, __nv_bfloat16* __restrict__ Ol,
             int N, int K) {
    extern __shared__ char smem[];
    float* Cs = (float*)smem;
    __shared__ float bias_s[128];

    const uint32_t sb = (uint32_t)__cvta_generic_to_shared(smem);
    const int tid  = threadIdx.x;
    const int wid  = tid >> 5;
    const int warpM = wid >> 2;
    const int warpN = wid & 3;
    const int m0 = blockIdx.y * 128, n0 = blockIdx.x * 128;

    if (tid < 128) bias_s[tid] = bias[n0 + tid];

    const int aRow = tid >> 1, aSeg = (tid & 1) << 1;
    const int bRow = tid >> 3, bSeg = (tid & 7) << 1;

    wmma::fragment<wmma::accumulator, 16, 16, 16, float> acc[4][2];
#pragma unroll
    for (int i = 0; i < 4; ++i)
#pragma unroll
        for (int j = 0; j < 2; ++j) wmma::fill_fragment(acc[i][j], 0.0f);

    const int nChunks = K >> 5;

    auto issue = [&](int c, int s) {
        const int kc = c << 5;
        const uint32_t st = sb + s * STAGE;
#pragma unroll
        for (int t = 0; t < 2; ++t) {
            const int seg = aSeg + t;
            cp16(st + SA_H + aRow*80 + seg*16, Ahp + (size_t)(m0 + aRow)*K + kc + seg*8);
            cp16(st + SA_L + aRow*80 + seg*16, Alp + (size_t)(m0 + aRow)*K + kc + seg*8);
        }
#pragma unroll
        for (int t = 0; t < 2; ++t) {
            const int seg = bSeg + t;
            cp16(st + SB_H + bRow*272 + seg*16, Whp + (size_t)(kc + bRow)*N + n0 + seg*8);
            cp16(st + SB_L + bRow*272 + seg*16, Wlp + (size_t)(kc + bRow)*N + n0 + seg*8);
        }
    };

    issue(0, 0);
    asm volatile("cp.async.commit_group;" ::: "memory");

    for (int c = 0; c < nChunks; ++c) {
        if (c + 1 < nChunks) {
            issue(c + 1, (c + 1) & 1);
            asm volatile("cp.async.commit_group;" ::: "memory");
            asm volatile("cp.async.wait_group 1;" ::: "memory");
        } else {
            asm volatile("cp.async.wait_group 0;" ::: "memory");
        }
        __syncthreads();

        const __nv_bfloat16* Ah = (const __nv_bfloat16*)(smem + (c & 1) * STAGE + SA_H);
        const __nv_bfloat16* Bh = (const __nv_bfloat16*)(smem + (c & 1) * STAGE + SB_H);
#pragma unroll
        for (int ks = 0; ks < 2; ++ks) {
            wmma::fragment<wmma::matrix_a, 16,16,16, __nv_bfloat16, wmma::row_major> fa_h[4], fa_l[4];
            wmma::fragment<wmma::matrix_b, 16,16,16, __nv_bfloat16, wmma::row_major> fb_h[2], fb_l[2];
#pragma unroll
            for (int i = 0; i < 4; ++i) {
                const __nv_bfloat16* ap = Ah + (warpM*64 + i*16)*LDA + ks*16;
                wmma::load_matrix_sync(fa_h[i], ap, LDA);
                wmma::load_matrix_sync(fa_l[i], ap + (SA_L - SA_H)/2, LDA);
            }
#pragma unroll
            for (int j = 0; j < 2; ++j) {
                const __nv_bfloat16* bp = Bh + (ks*16)*LDB + warpN*32 + j*16;
                wmma::load_matrix_sync(fb_h[j], bp, LDB);
                wmma::load_matrix_sync(fb_l[j], bp + (SB_L - SB_H)/2, LDB);
            }
#pragma unroll
            for (int i = 0; i < 4; ++i)
#pragma unroll
                for (int j = 0; j < 2; ++j) {
                    wmma::mma_sync(acc[i][j], fa_h[i], fb_h[j], acc[i][j]);
                    wmma::mma_sync(acc[i][j], fa_h[i], fb_l[j], acc[i][j]);
                    wmma::mma_sync(acc[i][j], fa_l[i], fb_h[j], acc[i][j]);
                }
        }
        __syncthreads();
    }

    // ---- epilogue ----
#pragma unroll
    for (int i = 0; i < 4; ++i)
#pragma unroll
        for (int j = 0; j < 2; ++j)
            wmma::store_matrix_sync(&Cs[(warpM*64 + i*16)*LDC + warpN*32 + j*16],
                                    acc[i][j], LDC, wmma::mem_row_major);
    __syncthreads();

    for (int idx = tid; idx < 128*32; idx += 256) {
        const int row = idx >> 5, c4 = (idx & 31) << 2;
        float r[4];
#pragma unroll
        for (int p = 0; p < 4; ++p) {
            float v = Cs[row*LDC + c4 + p] + bias_s[c4 + p];
            if (ACT == 1) v = 0.5f*v*(1.0f + erff(v*0.70710678118654752f));
            r[p] = v;
        }
        if (OSPLIT) {
            __nv_bfloat16 h[4], l[4];
#pragma unroll
            for (int p = 0; p < 4; ++p) splt(r[p], h[p], l[p]);
            *(uint2*)(Oh + (size_t)(m0 + row)*N + n0 + c4) = *(uint2*)h;
            *(uint2*)(Ol + (size_t)(m0 + row)*N + n0 + c4) = *(uint2*)l;
        } else {
            *(float4*)&C[(size_t)(m0 + row)*N + n0 + c4] = *(float4*)r;
        }
    }
}

// ---------------- embed: z = x @ W_P + b_P + W_pos ; emits fp32 + split ----------------
__global__ void embed_kernel(const float* __restrict__ x,
                             const float* __restrict__ W_P,
                             const float* __restrict__ b_P,
                             const float* __restrict__ W_pos,
                             __nv_bfloat16* __restrict__ zh,
                             __nv_bfloat16* __restrict__ zl) {
    int row = blockIdx.x;
    int d   = threadIdx.x;
    int q   = row % Q_;
    __shared__ float xs[P_];
    if (threadIdx.x < P_) xs[threadIdx.x] = x[row*P_ + threadIdx.x];
    __syncthreads();
    float acc = b_P[d] + W_pos[q*D_ + d];
#pragma unroll
    for (int p = 0; p < P_; ++p) acc += xs[p] * W_P[p*D_ + d];
    g_z[(size_t)row*D_ + d] = acc;
    __nv_bfloat16 h, l; splt(acc, h, l);
    zh[(size_t)row*D_ + d] = h;
    zl[(size_t)row*D_ + d] = l;
}

// ============== WMMA attention with telescoped score recompute ==============
// s_l = SCALE * sum_{i<=l} Q_i K_i^T + (l+1)*bias  — no score tensor in gmem.
// grid (H_, B_), 256 threads (8 warps; warp w owns rows w*16..w*16+15).
#define AT_SQH 0
#define AT_SQL 4096
#define AT_SKH 8192
#define AT_SKL 12288
#define AT_SVH 16384
#define AT_SVL 20480
#define AT_SS  24576
#define AT_LDS 132
#define AT_SPH 92160            // 24576 + 128*132*4
#define AT_SPL 124928
#define AT_SINV 157696
#define AT_SMEM 158208

__global__ __launch_bounds__(256)
void attn_wmma(const __nv_bfloat16* __restrict__ qh_g, const __nv_bfloat16* __restrict__ ql_g,
               const __nv_bfloat16* __restrict__ kh_g, const __nv_bfloat16* __restrict__ kl_g,
               const __nv_bfloat16* __restrict__ vh_g, const __nv_bfloat16* __restrict__ vl_g,
               const float* __restrict__ bias,
               __nv_bfloat16* __restrict__ oh, __nv_bfloat16* __restrict__ ol,
               int nLayers) {
    const int h = blockIdx.x, b = blockIdx.y;
    extern __shared__ char sm[];
    __nv_bfloat16* sqh = (__nv_bfloat16*)(sm + AT_SQH);
    __nv_bfloat16* sql = (__nv_bfloat16*)(sm + AT_SQL);
    __nv_bfloat16* skh = (__nv_bfloat16*)(sm + AT_SKH);
    __nv_bfloat16* skl = (__nv_bfloat16*)(sm + AT_SKL);
    __nv_bfloat16* svh = (__nv_bfloat16*)(sm + AT_SVH);
    __nv_bfloat16* svl = (__nv_bfloat16*)(sm + AT_SVL);
    float*         S   = (float*)(sm + AT_SS);
    __nv_bfloat16* ph  = (__nv_bfloat16*)(sm + AT_SPH);
    __nv_bfloat16* pl  = (__nv_bfloat16*)(sm + AT_SPL);
    float*         invs= (float*)(sm + AT_SINV);

    const int tid  = threadIdx.x;
    const int wid  = tid >> 5;
    const size_t base = ((size_t)b*Q_)*D_ + h*DK_;

    // stage V (once): row r, 8 bf16 per thread
    {
        const int r = tid >> 1, c0 = (tid & 1) * 8;
        *(uint4*)(svh + r*16 + c0) = *(const uint4*)(vh_g + base + (size_t)r*D_ + c0);
        *(uint4*)(svl + r*16 + c0) = *(const uint4*)(vl_g + base + (size_t)r*D_ + c0);
    }

    wmma::fragment<wmma::accumulator, 16, 16, 16, float> accS[8];
#pragma unroll
    for (int t = 0; t < 8; ++t) wmma::fill_fragment(accS[t], 0.0f);

    for (int i = 0; i < nLayers; ++i) {
        __syncthreads();   // previous iter's frag loads done before restage
        {
            const int r = tid >> 1, c0 = (tid & 1) * 8;
            const size_t g = (size_t)i*LSTRIDE + base + (size_t)r*D_ + c0;
            *(uint4*)(sqh + r*16 + c0) = *(const uint4*)(qh_g + g);
            *(uint4*)(sql + r*16 + c0) = *(const uint4*)(ql_g + g);
            *(uint4*)(skh + r*16 + c0) = *(const uint4*)(kh_g + g);
            *(uint4*)(skl + r*16 + c0) = *(const uint4*)(kl_g + g);
        }
        __syncthreads();

        wmma::fragment<wmma::matrix_a, 16,16,16, __nv_bfloat16, wmma::row_major> aH, aL;
        wmma::load_matrix_sync(aH, sqh + wid*16*16, 16);
        wmma::load_matrix_sync(aL, sql + wid*16*16, 16);
#pragma unroll
        for (int t = 0; t < 8; ++t) {
            wmma::fragment<wmma::matrix_b, 16,16,16, __nv_bfloat16, wmma::col_major> bH, bL;
            wmma::load_matrix_sync(bH, skh + t*16*16, 16);
            wmma::load_matrix_sync(bL, skl + t*16*16, 16);
            wmma::mma_sync(accS[t], aH, bH, accS[t]);
            wmma::mma_sync(accS[t], aH, bL, accS[t]);
            wmma::mma_sync(accS[t], aL, bH, accS[t]);
        }
    }

#pragma unroll
    for (int t = 0; t < 8; ++t)
        wmma::store_matrix_sync(&S[wid*16*AT_LDS + t*16], accS[t], AT_LDS, wmma::mem_row_major);
    __syncthreads();

    // softmax: 2 threads per row
    const int r = tid >> 1, half = tid & 1, j0 = half * 64;
    const float Lb = (float)nLayers;
    float mx = -1e30f;
    for (int jj = 0; jj < 64; ++jj) {
        const int j = j0 + jj;
        float s = S[r*AT_LDS + j] * SCALE_ + Lb * bias[r*Q_ + j];
        S[r*AT_LDS + j] = s;
        mx = fmaxf(mx, s);
    }
    mx = fmaxf(mx, __shfl_xor_sync(0xffffffffu, mx, 1));
    float sum = 0.f;
    for (int jj = 0; jj < 64; ++jj) {
        const int j = j0 + jj;
        float e = __expf(S[r*AT_LDS + j] - mx);
        __nv_bfloat16 eh, el; splt(e, eh, el);
        ph[r*128 + j] = eh;
        pl[r*128 + j] = el;
        sum += e;
    }
    sum += __shfl_xor_sync(0xffffffffu, sum, 1);
    if (half == 0) invs[r] = 1.0f / sum;
    __syncthreads();

    // AV: O = P @ V (128x16), warp w rows w*16..
    {
        wmma::fragment<wmma::accumulator, 16, 16, 16, float> accO;
        wmma::fill_fragment(accO, 0.0f);
#pragma unroll
        for (int t = 0; t < 8; ++t) {
            wmma::fragment<wmma::matrix_a, 16,16,16, __nv_bfloat16, wmma::row_major> pH, pL;
            wmma::fragment<wmma::matrix_b, 16,16,16, __nv_bfloat16, wmma::row_major> vH, vL;
            wmma::load_matrix_sync(pH, ph + wid*16*128 + t*16, 128);
            wmma::load_matrix_sync(pL, pl + wid*16*128 + t*16, 128);
            wmma::load_matrix_sync(vH, svh + t*16*16, 16);
            wmma::load_matrix_sync(vL, svl + t*16*16, 16);
            wmma::mma_sync(accO, pH, vH, accO);
            wmma::mma_sync(accO, pH, vL, accO);
            wmma::mma_sync(accO, pL, vH, accO);
        }
        __syncthreads();                       // S region free; reuse as O staging
        float* Os = S;
        wmma::store_matrix_sync(&Os[wid*16*16], accO, 16, wmma::mem_row_major);
        __syncthreads();

        if (tid < 128) {
            const float inv = invs[tid];
            __nv_bfloat16 hh[16], ll[16];
#pragma unroll
            for (int c = 0; c < 16; ++c) splt(Os[tid*16 + c] * inv, hh[c], ll[c]);
            const size_t ob = base + (size_t)tid*D_;
            *(uint4*)(oh + ob)     = *(uint4*)hh;
            *(uint4*)(oh + ob + 8) = *(uint4*)(hh + 8);
            *(uint4*)(ol + ob)     = *(uint4*)ll;
            *(uint4*)(ol + ob + 8) = *(uint4*)(ll + 8);
        }
    }
}

// ---------------- fused residual + LayerNorm ; emits fp32 + split ----------------
__global__ void ln_kernel(const float* __restrict__ resid,
                          const float* __restrict__ add,
                          const float* __restrict__ g,
                          const float* __restrict__ bta,
                          float* __restrict__ out,
                          __nv_bfloat16* __restrict__ zh,
                          __nv_bfloat16* __restrict__ zl) {
    const int row = blockIdx.x, d = threadIdx.x;
    __shared__ float w1s[8], w2s[8];
    float val = resid[(size_t)row*D_ + d] + add[(size_t)row*D_ + d];
    float s1 = val, s2 = val*val;
#pragma unroll
    for (int o = 16; o; o >>= 1) {
        s1 += __shfl_xor_sync(0xffffffffu, s1, o);
        s2 += __shfl_xor_sync(0xffffffffu, s2, o);
    }
    if ((d & 31) == 0) { w1s[d >> 5] = s1; w2s[d >> 5] = s2; }
    __syncthreads();
    float t1 = 0.f, t2 = 0.f;
#pragma unroll
    for (int i = 0; i < 8; ++i) { t1 += w1s[i]; t2 += w2s[i]; }
    float mu  = t1 * (1.0f/256.0f);
    float var = t2 * (1.0f/256.0f) - mu*mu;
    float r = (val - mu) * rsqrtf(var + EPS_) * g[d] + bta[d];
    out[(size_t)row*D_ + d] = r;
    __nv_bfloat16 h, l; splt(r, h, l);
    zh[(size_t)row*D_ + d] = h;
    zl[(size_t)row*D_ + d] = l;
}

// ---------------- launch ----------------
extern "C" void kernel_launch(void* const* d_in, const int* in_sizes, int n_in,
                              void* d_out, int out_size) {
    const float* x    = (const float*)d_in[0];
    const float* bias = (const float*)d_in[1];
    const float* W_P  = (const float*)d_in[2];
    const float* b_P  = (const float*)d_in[3];
    const float* Wpos = (const float*)d_in[4];
    const float* Wq   = (const float*)d_in[5];
    const float* bq   = (const float*)d_in[6];
    const float* Wk   = (const float*)d_in[7];
    const float* bk   = (const float*)d_in[8];
    const float* Wv   = (const float*)d_in[9];
    const float* bv   = (const float*)d_in[10];
    const float* Wo   = (const float*)d_in[11];
    const float* bo   = (const float*)d_in[12];
    const float* g1   = (const float*)d_in[13];
    const float* be1  = (const float*)d_in[14];
    const float* W1   = (const float*)d_in[15];
    const float* b1   = (const float*)d_in[16];
    const float* W2   = (const float*)d_in[17];
    const float* b2   = (const float*)d_in[18];
    const float* g2   = (const float*)d_in[19];
    const float* be2  = (const float*)d_in[20];
    float* out = (float*)d_out;

    float *z,*tb;
    __nv_bfloat16 *ah,*al,*bh2,*bl2,*wh,*wl,*qh,*ql,*kh,*kl,*vh,*vl;
    cudaGetSymbolAddress((void**)&z,  g_z);
    cudaGetSymbolAddress((void**)&tb, g_t);
    cudaGetSymbolAddress((void**)&ah, g_ah);
    cudaGetSymbolAddress((void**)&al, g_al);
    cudaGetSymbolAddress((void**)&bh2, g_bh);
    cudaGetSymbolAddress((void**)&bl2, g_bl);
    cudaGetSymbolAddress((void**)&wh, g_wh);
    cudaGetSymbolAddress((void**)&wl, g_wl);
    cudaGetSymbolAddress((void**)&qh, g_qh);
    cudaGetSymbolAddress((void**)&ql, g_ql);
    cudaGetSymbolAddress((void**)&kh, g_kh);
    cudaGetSymbolAddress((void**)&kl, g_kl);
    cudaGetSymbolAddress((void**)&vh, g_vh);
    cudaGetSymbolAddress((void**)&vl, g_vl);

    cudaFuncSetAttribute(attn_wmma, cudaFuncAttributeMaxDynamicSharedMemorySize, AT_SMEM);
    cudaFuncSetAttribute(gemm_bf<0,0>, cudaFuncAttributeMaxDynamicSharedMemorySize, SM_GEMM_BYTES);
    cudaFuncSetAttribute(gemm_bf<0,1>, cudaFuncAttributeMaxDynamicSharedMemorySize, SM_GEMM_BYTES);
    cudaFuncSetAttribute(gemm_bf<1,1>, cudaFuncAttributeMaxDynamicSharedMemorySize, SM_GEMM_BYTES);

    embed_kernel<<<MROWS, 256>>>(x, W_P, b_P, Wpos, ah, al);

    for (int l = 0; l < 3; ++l) {
        split_w6<<<dim3(128, 6), 256>>>(Wq + (size_t)l*D_*D_, Wk + (size_t)l*D_*D_,
                                        Wv + (size_t)l*D_*D_, Wo + (size_t)l*D_*D_,
                                        W1 + (size_t)l*D_*F_, W2 + (size_t)l*F_*D_,
                                        wh + (size_t)l*WSTRIDE, wl + (size_t)l*WSTRIDE);
    }

    dim3 gD(D_/128, MROWS/128);   // (2, 256)
    dim3 gF(F_/128, MROWS/128);   // (4, 256)

    for (int l = 0; l < 3; ++l) {
        const size_t wo_ = (size_t)l*WSTRIDE;
        const size_t ls  = (size_t)l*LSTRIDE;
        const float* bq_ = bq + (size_t)l*D_;
        const float* bk_ = bk + (size_t)l*D_;
        const float* bv_ = bv + (size_t)l*D_;
        const float* bo_ = bo + (size_t)l*D_;
        const float* b1_ = b1 + (size_t)l*F_;
        const float* b2_ = b2 + (size_t)l*D_;
        const float* g1_ = g1 + (size_t)l*D_;    const float* be1_ = be1 + (size_t)l*D_;
        const float* g2_ = g2 + (size_t)l*D_;    const float* be2_ = be2 + (size_t)l*D_;

        // QKV (split outputs; q/k persist per layer for score recompute)
        gemm_bf<0,1><<<gD, 256, SM_GEMM_BYTES>>>(ah, al, wh+wo_,        wl+wo_,        bq_, 0, qh+ls, ql+ls, D_, D_);
        gemm_bf<0,1><<<gD, 256, SM_GEMM_BYTES>>>(ah, al, wh+wo_+65536,  wl+wo_+65536,  bk_, 0, kh+ls, kl+ls, D_, D_);
        gemm_bf<0,1><<<gD, 256, SM_GEMM_BYTES>>>(ah, al, wh+wo_+131072, wl+wo_+131072, bv_, 0, vh,    vl,    D_, D_);

        attn_wmma<<<dim3(H_, B_), 256, AT_SMEM>>>(qh, ql, kh, kl, vh, vl, bias, ah, al, l + 1);

        gemm_bf<0,0><<<gD, 256, SM_GEMM_BYTES>>>(ah, al, wh+wo_+196608, wl+wo_+196608, bo_, tb, 0, 0, D_, D_);
        ln_kernel<<<MROWS, 256>>>(z, tb, g1_, be1_, z, ah, al);

        gemm_bf<1,1><<<gF, 256, SM_GEMM_BYTES>>>(ah, al, wh+wo_+262144, wl+wo_+262144, b1_, 0, bh2, bl2, F_, D_);
        gemm_bf<0,0><<<gD, 256, SM_GEMM_BYTES>>>(bh2, bl2, wh+wo_+393216, wl+wo_+393216, b2_, tb, 0, 0, D_, F_);
        ln_kernel<<<MROWS, 256>>>(z, tb, g2_, be2_, (l == 2) ? out : z, ah, al);
    }
}